// round 4
// baseline (speedup 1.0000x reference)
#include <cuda_runtime.h>
#include <climits>

// DTM layer via two-level weighted histogram quantile localization.
// Level-1 histogram uses warp-aggregated atomics (match_any + redux) to kill
// intra-warp same-bin ATOMS replays; level-2 atomics are range-predicated and
// nearly free. Weights quantized to u32 (x 2^19): deterministic integer sums.

constexpr int   NPTS    = 4096;           // points per batch (H*W)
constexpr int   THREADS = 512;
constexpr int   PPT     = NPTS / THREADS; // 8 points/thread, register-resident
constexpr int   NW      = THREADS / 32;   // 16 warps
constexpr int   NB      = 128;            // bins per level
constexpr float M0F     = 0.3f;
constexpr float RANGE   = 12.0f;          // safe upper bound on d2
constexpr float SCALE   = 524288.0f;      // 2^19: sum < 4096*2^19 = 2^31
constexpr float INV_SCALE = 1.0f / 524288.0f;

__device__ __forceinline__ float warp_sum(float v) {
    #pragma unroll
    for (int o = 16; o > 0; o >>= 1) v += __shfl_xor_sync(0xffffffffu, v, o);
    return v;
}

__global__ void __launch_bounds__(THREADS, 2) dtm_kernel(
    const float* __restrict__ input,   // (B, N, 2)
    const float* __restrict__ weight,  // (B, N)
    const float* __restrict__ grid,    // (N, 2)
    float* __restrict__ out)           // (B, N)
{
    __shared__ unsigned hist[2][NB];
    __shared__ unsigned wtot[4];       // scan totals (4 scan warps)
    __shared__ int      cbin[4];
    __shared__ unsigned ccum[4];
    __shared__ float    redS[NW], redW[NW];

    const int blk  = blockIdx.x;             // b * NPTS + q
    const int b    = blk >> 12;               // NPTS == 4096
    const int q    = blk & (NPTS - 1);
    const int t    = threadIdx.x;
    const int lane = t & 31, wid = t >> 5;

    const float gx = __ldg(&grid[2 * q]);
    const float gy = __ldg(&grid[2 * q + 1]);

    const float4* __restrict__ pts4 =
        reinterpret_cast<const float4*>(input + (size_t)b * NPTS * 2);
    const float2* __restrict__ wgt2 =
        reinterpret_cast<const float2*>(weight + (size_t)b * NPTS);

    // Load 8 points/thread (4 x float4 = 2 points each), all register-resident.
    float    d2[PPT];
    unsigned wi[PPT];
    #pragma unroll
    for (int k = 0; k < PPT / 2; k++) {
        const int u = t + k * THREADS;        // float4 index -> points 2u, 2u+1
        const float4 p = pts4[u];
        const float2 w = wgt2[u];
        float dx = p.x - gx, dy = p.y - gy;
        d2[2 * k]     = fmaf(dx, dx, dy * dy);
        dx = p.z - gx; dy = p.w - gy;
        d2[2 * k + 1] = fmaf(dx, dx, dy * dy);
        wi[2 * k]     = (unsigned)(w.x * SCALE);
        wi[2 * k + 1] = (unsigned)(w.y * SCALE);
    }

    if (t < NB) { hist[0][t] = 0u; hist[1][t] = 0u; }
    __syncthreads();

    // ============ Level 1: warp-aggregated weighted histogram ============
    {
        const float inv1 = (float)NB / RANGE;
        const unsigned lane_lt = (1u << lane) - 1u;
        #pragma unroll
        for (int k = 0; k < PPT; k++) {
            int bin = __float2int_rz(d2[k] * inv1);
            bin = min(bin, NB - 1);                          // d2 < RANGE anyway
            const unsigned gm = __match_any_sync(0xffffffffu, bin);
            const unsigned gsum = __reduce_add_sync(gm, wi[k]);
            if ((gm & lane_lt) == 0u)                        // group leader
                atomicAdd(&hist[0][bin], gsum);
        }
    }
    __syncthreads();

    // Scan level-1 histogram (threads 0..127), find crossing bin.
    unsigned v1 = 0, h1 = 0;
    if (t < NB) {
        h1 = hist[0][t];
        v1 = h1;
        #pragma unroll
        for (int o = 1; o < 32; o <<= 1) {
            const unsigned n = __shfl_up_sync(0xffffffffu, v1, o);
            if (lane >= o) v1 += n;
        }
        if (lane == 31) wtot[wid] = v1;
    }
    __syncthreads();

    const unsigned total = wtot[0] + wtot[1] + wtot[2] + wtot[3];
    unsigned target = (unsigned)(M0F * (float)total);

    if (t < NB) {
        unsigned off = 0;
        #pragma unroll
        for (int i = 0; i < 4; i++) if (i < wid) off += wtot[i];
        const unsigned cum = v1 + off;
        const unsigned bal = __ballot_sync(0xffffffffu, cum >= target);
        if (bal) {
            if (lane == __ffs(bal) - 1) { cbin[wid] = t; ccum[wid] = cum - h1; }
        } else if (lane == 0) {
            cbin[wid] = INT_MAX;
        }
    }
    __syncthreads();

    int bsel; unsigned csel;
    {
        bsel = cbin[0]; csel = ccum[0];
        if (cbin[1] < bsel) { bsel = cbin[1]; csel = ccum[1]; }
        if (cbin[2] < bsel) { bsel = cbin[2]; csel = ccum[2]; }
        if (cbin[3] < bsel) { bsel = cbin[3]; csel = ccum[3]; }
        if (bsel > NB - 1) bsel = NB - 1;
    }
    target -= csel;
    const float lo = (float)bsel * (RANGE / NB);
    __syncthreads();                           // wtot/cbin reuse in level 2

    // ============ Level 2: fine bins over [lo, lo + RANGE/NB) ============
    // Only ~N/NB points survive the range predicate -> atomics nearly free.
    {
        const float inv2 = (float)NB * (float)NB / RANGE;
        #pragma unroll
        for (int k = 0; k < PPT; k++) {
            const int bin = __float2int_rd((d2[k] - lo) * inv2);  // rd: no leak
            if ((unsigned)bin < (unsigned)NB) atomicAdd(&hist[1][bin], wi[k]);
        }
    }
    __syncthreads();

    unsigned v2 = 0;
    if (t < NB) {
        v2 = hist[1][t];
        #pragma unroll
        for (int o = 1; o < 32; o <<= 1) {
            const unsigned n = __shfl_up_sync(0xffffffffu, v2, o);
            if (lane >= o) v2 += n;
        }
        if (lane == 31) wtot[wid] = v2;
    }
    __syncthreads();

    if (t < NB) {
        unsigned off = 0;
        #pragma unroll
        for (int i = 0; i < 4; i++) if (i < wid) off += wtot[i];
        const unsigned bal = __ballot_sync(0xffffffffu, v2 + off >= target);
        if (bal) {
            if (lane == __ffs(bal) - 1) cbin[wid] = t;
        } else if (lane == 0) {
            cbin[wid] = INT_MAX;
        }
    }
    __syncthreads();

    int bsel2;
    {
        bsel2 = cbin[0];
        if (cbin[1] < bsel2) bsel2 = cbin[1];
        if (cbin[2] < bsel2) bsel2 = cbin[2];
        if (cbin[3] < bsel2) bsel2 = cbin[3];
        if (bsel2 > NB - 1) bsel2 = NB - 1;
    }
    // Threshold at center of selected fine bin: |t2 - t*| <= 3.7e-4 -> O(1e-7) err.
    const float t2 = lo + ((float)bsel2 + 0.5f) * (RANGE / (NB * NB));

    // ============ Epilogue: exact partial sums strictly below t2 ============
    float S = 0.f, Wl = 0.f;
    #pragma unroll
    for (int k = 0; k < PPT; k++) {
        if (d2[k] < t2) {
            const float wf = (float)wi[k] * INV_SCALE;
            S  = fmaf(d2[k], wf, S);
            Wl += wf;
        }
    }
    {
        const float rs = warp_sum(S);
        const float rw = warp_sum(Wl);
        if (lane == 0) { redS[wid] = rs; redW[wid] = rw; }
        __syncthreads();
        if (t == 0) {
            float Ss = 0.f, Ws = 0.f;
            #pragma unroll
            for (int i = 0; i < NW; i++) { Ss += redS[i]; Ws += redW[i]; }
            const float wb  = M0F * ((float)total * INV_SCALE);
            const float val = Ss + t2 * (wb - Ws);
            out[blk] = sqrtf(fmaxf(val, 0.f) / wb);
        }
    }
}

extern "C" void kernel_launch(void* const* d_in, const int* in_sizes, int n_in,
                              void* d_out, int out_size) {
    const float* input  = (const float*)d_in[0];   // (B, N, 2)
    const float* weight = (const float*)d_in[1];   // (B, N)
    const float* grid   = (const float*)d_in[2];   // (N, 2)
    float* out = (float*)d_out;                    // (B, N)

    const int total = in_sizes[1];                 // B * N queries (= out_size)
    dtm_kernel<<<total, THREADS>>>(input, weight, grid, out);
}

// round 5
// speedup vs baseline: 7.3049x; 7.3049x over previous
#include <cuda_runtime.h>
#include <climits>

// DTM layer via two-level weighted histogram quantile localization.
// Level-1 histogram uses 4-way bank-interleaved replicas (hist[bin*4+lane&3])
// plus register-level pair merging to cut ATOMS conflict replays ~6-8x with
// zero extra sync primitives. Weights quantized to u32 (x 2^19) so all
// histogram sums are deterministic integer atomics.

constexpr int   NPTS    = 4096;           // points per batch (H*W)
constexpr int   THREADS = 256;
constexpr int   PPT     = NPTS / THREADS; // 16 points/thread, register-resident
constexpr int   NW      = THREADS / 32;
constexpr int   NB      = 128;            // bins per level
constexpr int   REP     = 4;              // level-1 replicas (bank-interleaved)
constexpr float M0F     = 0.3f;
constexpr float RANGE   = 12.0f;          // safe upper bound on d2
constexpr float SCALE   = 524288.0f;      // 2^19: sum < 4096*2^19 = 2^31
constexpr float INV_SCALE = 1.0f / 524288.0f;

__device__ __forceinline__ float warp_sum(float v) {
    #pragma unroll
    for (int o = 16; o > 0; o >>= 1) v += __shfl_xor_sync(0xffffffffu, v, o);
    return v;
}

__global__ void __launch_bounds__(THREADS, 4) dtm_kernel(
    const float* __restrict__ input,   // (B, N, 2)
    const float* __restrict__ weight,  // (B, N)
    const float* __restrict__ grid,    // (N, 2)
    float* __restrict__ out)           // (B, N)
{
    __shared__ unsigned hist1[NB * REP];  // [bin][replica], word-interleaved
    __shared__ unsigned hist2[NB];
    __shared__ unsigned wtot[4];          // scan totals (4 scan warps)
    __shared__ int      cbin[4];
    __shared__ unsigned ccum[4];
    __shared__ float    redS[NW], redW[NW];

    const int blk  = blockIdx.x;              // b * NPTS + q
    const int b    = blk >> 12;                // NPTS == 4096
    const int q    = blk & (NPTS - 1);
    const int t    = threadIdx.x;
    const int lane = t & 31, wid = t >> 5;
    const int rep  = lane & (REP - 1);

    const float gx = __ldg(&grid[2 * q]);
    const float gy = __ldg(&grid[2 * q + 1]);

    const float4* __restrict__ pts4 =
        reinterpret_cast<const float4*>(input + (size_t)b * NPTS * 2);
    const float2* __restrict__ wgt2 =
        reinterpret_cast<const float2*>(weight + (size_t)b * NPTS);

    // Load 16 points/thread as 8 x float4 (2 points each) + 8 x float2 weights.
    float    d2[PPT];
    unsigned wi[PPT];
    #pragma unroll
    for (int k = 0; k < PPT / 2; k++) {
        const int u = t + k * THREADS;         // float4 index -> points 2u, 2u+1
        const float4 p = pts4[u];
        const float2 w = wgt2[u];
        float dx = p.x - gx, dy = p.y - gy;
        d2[2 * k]     = fmaf(dx, dx, dy * dy);
        dx = p.z - gx; dy = p.w - gy;
        d2[2 * k + 1] = fmaf(dx, dx, dy * dy);
        wi[2 * k]     = (unsigned)(w.x * SCALE);
        wi[2 * k + 1] = (unsigned)(w.y * SCALE);
    }

    // Zero histograms: 512 + 128 words, 256 threads.
    hist1[t] = 0u; hist1[t + 256] = 0u;
    if (t < NB) hist2[t] = 0u;
    __syncthreads();

    // ============ Level 1: replicated weighted histogram ============
    {
        const float inv1 = (float)NB / RANGE;
        #pragma unroll
        for (int k = 0; k < PPT; k += 2) {
            int b0 = min(__float2int_rz(d2[k]     * inv1), NB - 1);
            int b1 = min(__float2int_rz(d2[k + 1] * inv1), NB - 1);
            if (b0 == b1) {                    // adjacent points: usually same bin
                atomicAdd(&hist1[b0 * REP + rep], wi[k] + wi[k + 1]);
            } else {
                atomicAdd(&hist1[b0 * REP + rep], wi[k]);
                atomicAdd(&hist1[b1 * REP + rep], wi[k + 1]);
            }
        }
    }
    __syncthreads();

    // Scan level-1 histogram (threads 0..127), find crossing bin.
    unsigned v1 = 0, h1 = 0;
    if (t < NB) {
        h1 = hist1[t * REP] + hist1[t * REP + 1] + hist1[t * REP + 2] + hist1[t * REP + 3];
        v1 = h1;                               // warp-inclusive scan
        #pragma unroll
        for (int o = 1; o < 32; o <<= 1) {
            const unsigned n = __shfl_up_sync(0xffffffffu, v1, o);
            if (lane >= o) v1 += n;
        }
        if (lane == 31) wtot[wid] = v1;
    }
    __syncthreads();

    const unsigned total = wtot[0] + wtot[1] + wtot[2] + wtot[3];
    unsigned target = (unsigned)(M0F * (float)total);

    if (t < NB) {
        unsigned off = 0;
        #pragma unroll
        for (int i = 0; i < 4; i++) if (i < wid) off += wtot[i];
        const unsigned cum = v1 + off;         // global inclusive prefix
        const unsigned bal = __ballot_sync(0xffffffffu, cum >= target);
        if (bal) {
            if (lane == __ffs(bal) - 1) { cbin[wid] = t; ccum[wid] = cum - h1; }
        } else if (lane == 0) {
            cbin[wid] = INT_MAX;
        }
    }
    __syncthreads();

    int bsel; unsigned csel;
    {
        bsel = cbin[0]; csel = ccum[0];
        if (cbin[1] < bsel) { bsel = cbin[1]; csel = ccum[1]; }
        if (cbin[2] < bsel) { bsel = cbin[2]; csel = ccum[2]; }
        if (cbin[3] < bsel) { bsel = cbin[3]; csel = ccum[3]; }
        if (bsel > NB - 1) bsel = NB - 1;
    }
    target -= csel;
    const float lo = (float)bsel * (RANGE / NB);
    __syncthreads();                            // wtot/cbin reuse in level 2

    // ============ Level 2: fine bins over [lo, lo + RANGE/NB) ============
    // Only ~N/NB points survive the range predicate -> atomics nearly free.
    {
        const float inv2 = (float)NB * (float)NB / RANGE;
        #pragma unroll
        for (int k = 0; k < PPT; k++) {
            const int bin = __float2int_rd((d2[k] - lo) * inv2);  // rd: no leak
            if ((unsigned)bin < (unsigned)NB) atomicAdd(&hist2[bin], wi[k]);
        }
    }
    __syncthreads();

    unsigned v2 = 0;
    if (t < NB) {
        v2 = hist2[t];
        #pragma unroll
        for (int o = 1; o < 32; o <<= 1) {
            const unsigned n = __shfl_up_sync(0xffffffffu, v2, o);
            if (lane >= o) v2 += n;
        }
        if (lane == 31) wtot[wid] = v2;
    }
    __syncthreads();

    if (t < NB) {
        unsigned off = 0;
        #pragma unroll
        for (int i = 0; i < 4; i++) if (i < wid) off += wtot[i];
        const unsigned bal = __ballot_sync(0xffffffffu, v2 + off >= target);
        if (bal) {
            if (lane == __ffs(bal) - 1) cbin[wid] = t;
        } else if (lane == 0) {
            cbin[wid] = INT_MAX;
        }
    }
    __syncthreads();

    int bsel2;
    {
        bsel2 = cbin[0];
        if (cbin[1] < bsel2) bsel2 = cbin[1];
        if (cbin[2] < bsel2) bsel2 = cbin[2];
        if (cbin[3] < bsel2) bsel2 = cbin[3];
        if (bsel2 > NB - 1) bsel2 = NB - 1;
    }
    // Threshold at center of selected fine bin: |t2 - t*| <= 3.7e-4 -> O(1e-7) err.
    const float t2 = lo + ((float)bsel2 + 0.5f) * (RANGE / (NB * NB));

    // ============ Epilogue: exact partial sums strictly below t2 ============
    float S = 0.f, Wl = 0.f;
    #pragma unroll
    for (int k = 0; k < PPT; k++) {
        if (d2[k] < t2) {
            const float wf = (float)wi[k] * INV_SCALE;
            S  = fmaf(d2[k], wf, S);
            Wl += wf;
        }
    }
    {
        const float rs = warp_sum(S);
        const float rw = warp_sum(Wl);
        if (lane == 0) { redS[wid] = rs; redW[wid] = rw; }
        __syncthreads();
        if (t == 0) {
            float Ss = 0.f, Ws = 0.f;
            #pragma unroll
            for (int i = 0; i < NW; i++) { Ss += redS[i]; Ws += redW[i]; }
            const float wb  = M0F * ((float)total * INV_SCALE);
            const float val = Ss + t2 * (wb - Ws);
            out[blk] = sqrtf(fmaxf(val, 0.f) / wb);
        }
    }
}

extern "C" void kernel_launch(void* const* d_in, const int* in_sizes, int n_in,
                              void* d_out, int out_size) {
    const float* input  = (const float*)d_in[0];   // (B, N, 2)
    const float* weight = (const float*)d_in[1];   // (B, N)
    const float* grid   = (const float*)d_in[2];   // (N, 2)
    float* out = (float*)d_out;                    // (B, N)

    const int total = in_sizes[1];                 // B * N queries (= out_size)
    dtm_kernel<<<total, THREADS>>>(input, weight, grid, out);
}